// round 1
// baseline (speedup 1.0000x reference)
#include <cuda_runtime.h>
#include <cuda_bf16.h>

#define VDIM 128
#define NCH 20
#define NUM_EMB (VDIM * VDIM * VDIM)
#define TPB 320   // 64 points per block, 5 threads per point

__global__ __launch_bounds__(TPB) void dense_grid_interp_kernel(
    const float* __restrict__ x,     // [n, 3]
    const float* __restrict__ grid,  // [NUM_EMB, 20]
    float* __restrict__ out,         // [n, 20]
    int n)
{
    int t = blockIdx.x * TPB + threadIdx.x;
    int p = t / 5;        // point index
    int c = t - p * 5;    // which float4 of the 20 channels
    if (p >= n) return;

    float px = __ldg(x + 3 * p + 0);
    float py = __ldg(x + 3 * p + 1);
    float pz = __ldg(x + 3 * p + 2);

    // (x - lo)/len * V  ==  (x+1)*64  (exact in fp32)
    float fx = (px + 1.0f) * 64.0f;
    float fy = (py + 1.0f) * 64.0f;
    float fz = (pz + 1.0f) * 64.0f;

    float gx = floorf(fx), gy = floorf(fy), gz = floorf(fz);
    float wx1 = fx - gx, wy1 = fy - gy, wz1 = fz - gz;
    float wx0 = 1.0f - wx1, wy0 = 1.0f - wy1, wz0 = 1.0f - wz1;

    int ix = (int)gx, iy = (int)gy, iz = (int)gz;
    int base = ix + (iy << 7) + (iz << 14);

    int f0 = base;
    int f1 = base + 1;
    int f2 = base + VDIM;
    int f3 = base + VDIM + 1;
    int f4 = base + VDIM * VDIM;
    int f5 = f4 + 1;
    int f6 = f4 + VDIM;
    int f7 = f6 + 1;

    // JAX gather clamps out-of-bounds flat indices (gp+1 can reach 128)
    const int last = NUM_EMB - 1;
    f0 = min(f0, last); f1 = min(f1, last); f2 = min(f2, last); f3 = min(f3, last);
    f4 = min(f4, last); f5 = min(f5, last); f6 = min(f6, last); f7 = min(f7, last);

    const float4* __restrict__ g4 = (const float4*)grid;
    // grid row = 20 floats = 5 float4; this thread reads float4 #c of each corner
    float4 q0 = __ldg(g4 + f0 * 5 + c);
    float4 q1 = __ldg(g4 + f1 * 5 + c);
    float4 q2 = __ldg(g4 + f2 * 5 + c);
    float4 q3 = __ldg(g4 + f3 * 5 + c);
    float4 q4 = __ldg(g4 + f4 * 5 + c);
    float4 q5 = __ldg(g4 + f5 * 5 + c);
    float4 q6 = __ldg(g4 + f6 * 5 + c);
    float4 q7 = __ldg(g4 + f7 * 5 + c);

    float w0 = wx0 * wy0 * wz0;
    float w1 = wx1 * wy0 * wz0;
    float w2 = wx0 * wy1 * wz0;
    float w3 = wx1 * wy1 * wz0;
    float w4 = wx0 * wy0 * wz1;
    float w5 = wx1 * wy0 * wz1;
    float w6 = wx0 * wy1 * wz1;
    float w7 = wx1 * wy1 * wz1;

    float4 r;
    r.x = w0*q0.x + w1*q1.x + w2*q2.x + w3*q3.x + w4*q4.x + w5*q5.x + w6*q6.x + w7*q7.x;
    r.y = w0*q0.y + w1*q1.y + w2*q2.y + w3*q3.y + w4*q4.y + w5*q5.y + w6*q6.y + w7*q7.y;
    r.z = w0*q0.z + w1*q1.z + w2*q2.z + w3*q3.z + w4*q4.z + w5*q5.z + w6*q6.z + w7*q7.z;
    r.w = w0*q0.w + w1*q1.w + w2*q2.w + w3*q3.w + w4*q4.w + w5*q5.w + w6*q6.w + w7*q7.w;

    ((float4*)out)[p * 5 + c] = r;
}

extern "C" void kernel_launch(void* const* d_in, const int* in_sizes, int n_in,
                              void* d_out, int out_size) {
    const float* x    = (const float*)d_in[0];   // [n, 3] float32
    const float* grid = (const float*)d_in[1];   // [NUM_EMB, 20] float32
    float* out = (float*)d_out;                  // [n, 20] float32

    int n = in_sizes[0] / 3;
    long long total_threads = (long long)n * 5;
    int blocks = (int)((total_threads + TPB - 1) / TPB);
    dense_grid_interp_kernel<<<blocks, TPB>>>(x, grid, out, n);
}